// round 13
// baseline (speedup 1.0000x reference)
#include <cuda_runtime.h>
#include <cuda_bf16.h>
#include <math.h>
#include <stdint.h>

// Problem constants
#define BB   2
#define SS   2048
#define HH   1024
#define NHH  16
#define HDD  64
#define MM   (BB * SS)          // 4096 rows

typedef __nv_bfloat16 bf16;

// ---------------------------------------------------------------------------
// Scratch (device globals: allocation-free contract)
// ---------------------------------------------------------------------------
__device__ __align__(256) bf16 g_hs[3][MM * HH];
__device__ __align__(256) bf16 g_wsp[12][HH * HH];
__device__ __align__(256) bf16 g_qkv[6][MM * HH];   // q0,q1,k0,k1,v0,v1
__device__ __align__(256) bf16 g_cx[2][MM * HH];    // ctx limbs

// ---------------------------------------------------------------------------
// Limb splits
// ---------------------------------------------------------------------------
__device__ __forceinline__ void split3_body(
    float4 a, bf16* L0, bf16* L1, bf16* L2, size_t i)
{
    float v[4] = {a.x, a.y, a.z, a.w};
    __align__(8) bf16 o0[4], o1[4], o2[4];
#pragma unroll
    for (int t = 0; t < 4; ++t) {
        float x = v[t];
        bf16 c0 = __float2bfloat16(x);
        float r = x - __bfloat162float(c0);
        bf16 c1 = __float2bfloat16(r);
        r -= __bfloat162float(c1);
        bf16 c2 = __float2bfloat16(r);
        o0[t] = c0; o1[t] = c1; o2[t] = c2;
    }
    *(uint2*)(L0 + 4 * i) = *(uint2*)o0;
    *(uint2*)(L1 + 4 * i) = *(uint2*)o1;
    *(uint2*)(L2 + 4 * i) = *(uint2*)o2;
}

__global__ void __launch_bounds__(256) split_hs(
    const float4* __restrict__ A,
    bf16* __restrict__ L0, bf16* __restrict__ L1, bf16* __restrict__ L2, int n4)
{
    int i = blockIdx.x * 256 + threadIdx.x;
    if (i >= n4) return;
    split3_body(A[i], L0, L1, L2, (size_t)i);
}

struct WSplitArgs {
    const float4* a[4];
    const float4* b[4];
    bf16 *l0[4], *l1[4], *l2[4];
};

__global__ void __launch_bounds__(256) split_w4(WSplitArgs args, int n4)
{
    const int t = blockIdx.y;
    int i = blockIdx.x * 256 + threadIdx.x;
    if (i >= n4) return;
    float4 a = args.a[t][i];
    float4 b = args.b[t][i];
    a.x += b.x; a.y += b.y; a.z += b.z; a.w += b.w;
    split3_body(a, args.l0[t], args.l1[t], args.l2[t], (size_t)i);
}

// ---------------------------------------------------------------------------
// mma.sync helpers
// ---------------------------------------------------------------------------
__device__ __forceinline__ void ldsm4(uint32_t* r, uint32_t addr) {
    asm volatile("ldmatrix.sync.aligned.m8n8.x4.shared.b16 {%0,%1,%2,%3}, [%4];"
                 : "=r"(r[0]), "=r"(r[1]), "=r"(r[2]), "=r"(r[3]) : "r"(addr));
}
__device__ __forceinline__ void ldsm4t(uint32_t* r, uint32_t addr) {
    asm volatile("ldmatrix.sync.aligned.m8n8.x4.trans.shared.b16 {%0,%1,%2,%3}, [%4];"
                 : "=r"(r[0]), "=r"(r[1]), "=r"(r[2]), "=r"(r[3]) : "r"(addr));
}
__device__ __forceinline__ void hmma(float* c, const uint32_t* a,
                                     uint32_t b0, uint32_t b1) {
    asm volatile(
        "mma.sync.aligned.m16n8k16.row.col.f32.bf16.bf16.f32 "
        "{%0,%1,%2,%3}, {%4,%5,%6,%7}, {%8,%9}, {%0,%1,%2,%3};"
        : "+f"(c[0]), "+f"(c[1]), "+f"(c[2]), "+f"(c[3])
        : "r"(a[0]), "r"(a[1]), "r"(a[2]), "r"(a[3]), "r"(b0), "r"(b1));
}

// ---------------------------------------------------------------------------
// HMMA multi-limb GEMM, 2 CTAs/SM, 4-stage K16 pipeline (wait_group 2 keeps
// two loads in flight; the per-stage barrier never exposes load latency).
// Tile = 128 rows x 32B; swizzle phys = r*32 + ((ch ^ ((r>>2)&1))<<4) —
// conflict-free for every ldmatrix phase (8 rows span all eight 16B slots).
// 8 warps (2x4), warp 64x32.
// ---------------------------------------------------------------------------
template <int NL, bool LIMB>
__global__ void __launch_bounds__(256, 2) mma_gemm(
    const bf16* __restrict__ a0, const bf16* __restrict__ a1,
    const bf16* __restrict__ a2,
    const bf16* __restrict__ b0, const bf16* __restrict__ b1,
    const bf16* __restrict__ b2,
    float* __restrict__ C, bf16* __restrict__ L0, bf16* __restrict__ L1)
{
    constexpr int NT     = 2 * NL;
    constexpr int TILEB  = 128 * 32;      // 4096
    constexpr int STAGEB = NT * TILEB;
    constexpr int NS     = 64;            // K16 stages

    extern __shared__ __align__(128) char smem[];
    const uint32_t sb = (uint32_t)__cvta_generic_to_shared(smem);

    const int tid  = threadIdx.x;
    const int lane = tid & 31;
    const int wid  = tid >> 5;
    const int wm   = wid >> 2;
    const int wn   = wid & 3;
    const int m0   = blockIdx.y * 128;
    const int n0   = blockIdx.x * 128;

    const bf16* srcs[NT];
    srcs[0] = a0 + (size_t)m0 * 1024;
    srcs[1] = a1 + (size_t)m0 * 1024;
    if constexpr (NL == 3) {
        srcs[2] = a2 + (size_t)m0 * 1024;
        srcs[3] = b0 + (size_t)n0 * 1024;
        srcs[4] = b1 + (size_t)n0 * 1024;
        srcs[5] = b2 + (size_t)n0 * 1024;
    } else {
        srcs[2] = b0 + (size_t)n0 * 1024;
        srcs[3] = b1 + (size_t)n0 * 1024;
    }

    auto load_stage = [&](int s) {
        const int k0 = s * 16;
        const uint32_t dstb = sb + (s & 3) * STAGEB;
#pragma unroll
        for (int i = 0; i < NT; ++i) {          // 256 chunks per tile
            const int idx = tid + 256 * i;
            const int t   = idx >> 8;
            const int c   = idx & 255;
            const int row = c >> 1;
            const int ch  = c & 1;
            const uint32_t phys = (uint32_t)(row * 32 + ((ch ^ ((row >> 2) & 1)) << 4));
            uint32_t dst = dstb + t * TILEB + phys;
            const void* src = srcs[t] + (size_t)row * 1024 + k0 + ch * 8;
            asm volatile("cp.async.cg.shared.global [%0], [%1], 16;"
                         :: "r"(dst), "l"(src) : "memory");
        }
        asm volatile("cp.async.commit_group;" ::: "memory");
    };

    float acc[4][4][4];
#pragma unroll
    for (int mf = 0; mf < 4; ++mf)
#pragma unroll
        for (int nf = 0; nf < 4; ++nf)
#pragma unroll
            for (int r = 0; r < 4; ++r) acc[mf][nf][r] = 0.0f;

    load_stage(0);
    load_stage(1);
    load_stage(2);

    for (int s = 0; s < NS; ++s) {
        if (s < NS - 2)       asm volatile("cp.async.wait_group 2;" ::: "memory");
        else if (s == NS - 2) asm volatile("cp.async.wait_group 1;" ::: "memory");
        else                  asm volatile("cp.async.wait_group 0;" ::: "memory");
        __syncthreads();
        if (s + 3 < NS) load_stage(s + 3);   // buf (s+3)&3: readers done at barrier

        const uint32_t st = sb + (s & 3) * STAGEB;
        uint32_t Af[NL][4][4];
        uint32_t Bf[NL][2][4];
#pragma unroll
        for (int l = 0; l < NL; ++l) {
#pragma unroll
            for (int mf = 0; mf < 4; ++mf) {
                const int r  = wm * 64 + mf * 16 + (lane & 15);
                const int ch = (lane >> 4) & 1;
                ldsm4(Af[l][mf], st + l * TILEB
                      + r * 32 + ((ch ^ ((r >> 2) & 1)) << 4));
            }
#pragma unroll
            for (int pr = 0; pr < 2; ++pr) {
                const int r  = wn * 32 + pr * 16 + ((lane >> 4) & 1) * 8 + (lane & 7);
                const int ch = (lane >> 3) & 1;
                ldsm4(Bf[l][pr], st + (NL + l) * TILEB
                      + r * 32 + ((ch ^ ((r >> 2) & 1)) << 4));
            }
        }
#pragma unroll
        for (int i = 0; i < NL; ++i)
#pragma unroll
            for (int j = 0; j < NL; ++j) {
                if (i + j >= NL) continue;
#pragma unroll
                for (int mf = 0; mf < 4; ++mf)
#pragma unroll
                    for (int pr = 0; pr < 2; ++pr) {
                        hmma(acc[mf][pr * 2 + 0], Af[i][mf], Bf[j][pr][0], Bf[j][pr][1]);
                        hmma(acc[mf][pr * 2 + 1], Af[i][mf], Bf[j][pr][2], Bf[j][pr][3]);
                    }
            }
    }

    const int mrow = m0 + wm * 64 + (lane >> 2);
    const int ncol = n0 + wn * 32 + (lane & 3) * 2;
#pragma unroll
    for (int mf = 0; mf < 4; ++mf)
#pragma unroll
        for (int nf = 0; nf < 4; ++nf) {
            const size_t r0 = (size_t)(mrow + mf * 16) * 1024 + ncol + nf * 8;
            const size_t r1 = r0 + 8 * 1024;
            if constexpr (LIMB) {
                float v0 = acc[mf][nf][0], v1 = acc[mf][nf][1];
                float v2 = acc[mf][nf][2], v3 = acc[mf][nf][3];
                __nv_bfloat162 h0 = __floats2bfloat162_rn(v0, v1);
                __nv_bfloat162 g0 = __floats2bfloat162_rn(
                    v0 - __bfloat162float(h0.x), v1 - __bfloat162float(h0.y));
                __nv_bfloat162 h1 = __floats2bfloat162_rn(v2, v3);
                __nv_bfloat162 g1 = __floats2bfloat162_rn(
                    v2 - __bfloat162float(h1.x), v3 - __bfloat162float(h1.y));
                *(uint32_t*)(L0 + r0) = *(uint32_t*)&h0;
                *(uint32_t*)(L1 + r0) = *(uint32_t*)&g0;
                *(uint32_t*)(L0 + r1) = *(uint32_t*)&h1;
                *(uint32_t*)(L1 + r1) = *(uint32_t*)&g1;
            } else {
                *(float2*)(C + r0) = make_float2(acc[mf][nf][0], acc[mf][nf][1]);
                *(float2*)(C + r1) = make_float2(acc[mf][nf][2], acc[mf][nf][3]);
            }
        }
}

// ---------------------------------------------------------------------------
// HMMA flash attention (reverted to 256-thread / 8-warp structure):
// wm=wid>>1 (32 q-rows), wn=wid&1 (64 k-cols). Split K/V prefetch,
// single-pass softmax merge, 2 barriers per iteration. 144B-padded rows.
// Product-major HMMA ordering (same-acc distance 4).
// ---------------------------------------------------------------------------
#define ATILE  18432          // 128 rows * 144B
#define KSTAGE (2 * ATILE)    // 2 limbs

__global__ void __launch_bounds__(256, 1) attn_mma(
    const bf16* __restrict__ q0l, const bf16* __restrict__ q1l,
    const bf16* __restrict__ k0l, const bf16* __restrict__ k1l,
    const bf16* __restrict__ v0l, const bf16* __restrict__ v1l,
    const float* __restrict__ mask,
    bf16* __restrict__ cx0, bf16* __restrict__ cx1)
{
    extern __shared__ __align__(128) char smem[];
    const uint32_t sb = (uint32_t)__cvta_generic_to_shared(smem);
    const uint32_t kK   = sb;                        // K: 2 stages x 2 limbs
    const uint32_t kV   = sb + 2 * KSTAGE;           // V: 2 stages x 2 limbs
    const uint32_t qbse = sb + 4 * KSTAGE;           // Q: 2 limbs
    float* red = (float*)(smem + 4 * KSTAGE + 2 * ATILE);  // [2][128][2] (m,l)

    const int tid  = threadIdx.x;
    const int lane = tid & 31;
    const int wid  = tid >> 5;
    const int wm   = wid >> 1;
    const int wn   = wid & 1;
    const int qt = blockIdx.x, h = blockIdx.y, b = blockIdx.z;
    const int q0r = qt * 128;

    const size_t hb = (size_t)b * SS * HH + (size_t)h * HDD;
    const bf16* qsrc[2] = {q0l + hb + (size_t)q0r * HH, q1l + hb + (size_t)q0r * HH};
    const bf16* ksrc[2] = {k0l + hb, k1l + hb};
    const bf16* vsrc[2] = {v0l + hb, v1l + hb};
    const float* maskb = mask + (size_t)b * SS * SS;

    auto load_k = [&](int s) {
        const int k00 = s * 128;
        const uint32_t dstb = kK + (s & 1) * KSTAGE;
#pragma unroll
        for (int i = 0; i < 8; ++i) {
            const int idx = tid + 256 * i;
            const int limb = idx >> 10;
            const int rem  = idx & 1023;
            const int r = rem >> 3, c = rem & 7;
            uint32_t dst = dstb + limb * ATILE + r * 144 + c * 16;
            const void* src = ksrc[limb] + (size_t)(k00 + r) * HH + c * 8;
            asm volatile("cp.async.cg.shared.global [%0], [%1], 16;"
                         :: "r"(dst), "l"(src) : "memory");
        }
    };
    auto load_v = [&](int s) {
        const int k00 = s * 128;
        const uint32_t dstb = kV + (s & 1) * KSTAGE;
#pragma unroll
        for (int i = 0; i < 8; ++i) {
            const int idx = tid + 256 * i;
            const int limb = idx >> 10;
            const int rem  = idx & 1023;
            const int r = rem >> 3, c = rem & 7;
            uint32_t dst = dstb + limb * ATILE + r * 144 + c * 16;
            const void* src = vsrc[limb] + (size_t)(k00 + r) * HH + c * 8;
            asm volatile("cp.async.cg.shared.global [%0], [%1], 16;"
                         :: "r"(dst), "l"(src) : "memory");
        }
    };

    // Prologue: G0 = {Q, K0, V0}; G1 = {K1}
#pragma unroll
    for (int i = 0; i < 8; ++i) {
        const int idx = tid + 256 * i;
        const int limb = idx >> 10;
        const int rem  = idx & 1023;
        const int r = rem >> 3, c = rem & 7;
        uint32_t dst = qbse + limb * ATILE + r * 144 + c * 16;
        const void* src = qsrc[limb] + (size_t)r * HH + c * 8;
        asm volatile("cp.async.cg.shared.global [%0], [%1], 16;"
                     :: "r"(dst), "l"(src) : "memory");
    }
    load_k(0);
    load_v(0);
    asm volatile("cp.async.commit_group;" ::: "memory");
    load_k(1);
    asm volatile("cp.async.commit_group;" ::: "memory");

    float O[2][8][4];
#pragma unroll
    for (int mf = 0; mf < 2; ++mf)
#pragma unroll
        for (int dn = 0; dn < 8; ++dn)
#pragma unroll
            for (int r = 0; r < 4; ++r) O[mf][dn][r] = 0.0f;
    float mst[4] = {-INFINITY, -INFINITY, -INFINITY, -INFINITY};
    float lst[4] = {0.0f, 0.0f, 0.0f, 0.0f};

    const int rloc = (lane >> 2);
    const float scale = 0.125f;

    for (int s = 0; s < 16; ++s) {
        if (s < 15) asm volatile("cp.async.wait_group 1;" ::: "memory");
        else        asm volatile("cp.async.wait_group 0;" ::: "memory");
        __syncthreads();                              // barrier A

        if (s + 1 < 16) {
            load_v(s + 1);
            asm volatile("cp.async.commit_group;" ::: "memory");
        }

        const uint32_t kst = kK + (s & 1) * KSTAGE;
        const uint32_t vst = kV + (s & 1) * KSTAGE;

        // ---- QK^T ----
        float S[2][8][4];
#pragma unroll
        for (int mf = 0; mf < 2; ++mf)
#pragma unroll
            for (int nf = 0; nf < 8; ++nf)
#pragma unroll
                for (int r = 0; r < 4; ++r) S[mf][nf][r] = 0.0f;

#pragma unroll
        for (int ch = 0; ch < 4; ++ch) {
            uint32_t A[2][2][4];
#pragma unroll
            for (int l = 0; l < 2; ++l)
#pragma unroll
                for (int mf = 0; mf < 2; ++mf)
                    ldsm4(A[l][mf], qbse + l * ATILE
                          + (wm * 32 + mf * 16 + (lane & 15)) * 144
                          + ch * 32 + ((lane >> 4) & 1) * 16);
#pragma unroll
            for (int bp = 0; bp < 4; ++bp) {
                uint32_t B0[4], B1[4];
                const uint32_t ba = kst
                    + (wn * 64 + bp * 16 + ((lane >> 4) & 1) * 8 + (lane & 7)) * 144
                    + ((lane >> 3) & 1) * 16 + ch * 32;
                ldsm4(B0, ba);
                ldsm4(B1, ba + ATILE);
                // product-major: same-acc reuse distance 4
#pragma unroll
                for (int mf = 0; mf < 2; ++mf) {      // q0k0
                    hmma(S[mf][2 * bp + 0], A[0][mf], B0[0], B0[1]);
                    hmma(S[mf][2 * bp + 1], A[0][mf], B0[2], B0[3]);
                }
#pragma unroll
                for (int mf = 0; mf < 2; ++mf) {      // q0k1
                    hmma(S[mf][2 * bp + 0], A[0][mf], B1[0], B1[1]);
                    hmma(S[mf][2 * bp + 1], A[0][mf], B1[2], B1[3]);
                }
#pragma unroll
                for (int mf = 0; mf < 2; ++mf) {      // q1k0
                    hmma(S[mf][2 * bp + 0], A[1][mf], B0[0], B0[1]);
                    hmma(S[mf][2 * bp + 1], A[1][mf], B0[2], B0[3]);
                }
            }
        }

        // ---- scale + mask + local max ----
        float mloc[4] = {-INFINITY, -INFINITY, -INFINITY, -INFINITY};
#pragma unroll
        for (int mf = 0; mf < 2; ++mf)
#pragma unroll
            for (int rh = 0; rh < 2; ++rh) {
                const int row = q0r + wm * 32 + mf * 16 + rh * 8 + rloc;
                const float* mrp = maskb + (size_t)row * SS + s * 128 + wn * 64
                                   + (lane & 3) * 2;
                const int sl = mf * 2 + rh;
#pragma unroll
                for (int nf = 0; nf < 8; ++nf) {
                    float2 mv = *(const float2*)(mrp + nf * 8);
                    float a = fmaf(S[mf][nf][rh * 2 + 0], scale, mv.x);
                    float c = fmaf(S[mf][nf][rh * 2 + 1], scale, mv.y);
                    S[mf][nf][rh * 2 + 0] = a;
                    S[mf][nf][rh * 2 + 1] = c;
                    mloc[sl] = fmaxf(mloc[sl], fmaxf(a, c));
                }
            }
#pragma unroll
        for (int off = 1; off < 4; off <<= 1)
#pragma unroll
            for (int sl = 0; sl < 4; ++sl)
                mloc[sl] = fmaxf(mloc[sl], __shfl_xor_sync(0xffffffffu, mloc[sl], off));

        // ---- exp with LOCAL max + local sum (pre-barrier) ----
        float lw[4];
#pragma unroll
        for (int mf = 0; mf < 2; ++mf)
#pragma unroll
            for (int rh = 0; rh < 2; ++rh) {
                const int sl = mf * 2 + rh;
                float ls = 0.0f;
#pragma unroll
                for (int nf = 0; nf < 8; ++nf) {
                    float a = __expf(S[mf][nf][rh * 2 + 0] - mloc[sl]);
                    float c = __expf(S[mf][nf][rh * 2 + 1] - mloc[sl]);
                    S[mf][nf][rh * 2 + 0] = a;
                    S[mf][nf][rh * 2 + 1] = c;
                    ls += a + c;
                }
                lw[sl] = ls;
            }
#pragma unroll
        for (int off = 1; off < 4; off <<= 1)
#pragma unroll
            for (int sl = 0; sl < 4; ++sl)
                lw[sl] += __shfl_xor_sync(0xffffffffu, lw[sl], off);

        if ((lane & 3) == 0) {
#pragma unroll
            for (int mf = 0; mf < 2; ++mf)
#pragma unroll
                for (int rh = 0; rh < 2; ++rh) {
                    const int rr = wm * 32 + mf * 16 + rh * 8 + rloc;
                    red[wn * 256 + rr * 2 + 0] = mloc[mf * 2 + rh];
                    red[wn * 256 + rr * 2 + 1] = lw[mf * 2 + rh];
                }
        }
        __syncthreads();                              // barrier B

        if (s + 2 < 16) {
            load_k(s + 2);
            asm volatile("cp.async.commit_group;" ::: "memory");
        }

        // ---- cross-half merge ----
        float alpha[4], beta[4];
#pragma unroll
        for (int mf = 0; mf < 2; ++mf)
#pragma unroll
            for (int rh = 0; rh < 2; ++rh) {
                const int sl = mf * 2 + rh;
                const int rr = wm * 32 + mf * 16 + rh * 8 + rloc;
                const float mp = red[(wn ^ 1) * 256 + rr * 2 + 0];
                const float lp = red[(wn ^ 1) * 256 + rr * 2 + 1];
                const float mnew = fmaxf(mst[sl], fmaxf(mloc[sl], mp));
                alpha[sl] = __expf(mst[sl] - mnew);
                beta[sl]  = __expf(mloc[sl] - mnew);
                lst[sl] = lst[sl] * alpha[sl] + lw[sl] * beta[sl]
                          + lp * __expf(mp - mnew);
                mst[sl] = mnew;
            }
#pragma unroll
        for (int mf = 0; mf < 2; ++mf)
#pragma unroll
            for (int dn = 0; dn < 8; ++dn) {
                O[mf][dn][0] *= alpha[mf * 2 + 0];
                O[mf][dn][1] *= alpha[mf * 2 + 0];
                O[mf][dn][2] *= alpha[mf * 2 + 1];
                O[mf][dn][3] *= alpha[mf * 2 + 1];
            }

        // ---- PV (P scaled by beta during frag build) ----
#pragma unroll
        for (int kch = 0; kch < 4; ++kch) {
            uint32_t P0[2][4], P1[2][4];
#pragma unroll
            for (int mf = 0; mf < 2; ++mf) {
                const float b0s = beta[mf * 2 + 0];
                const float b1s = beta[mf * 2 + 1];
#pragma unroll
                for (int half = 0; half < 2; ++half) {
                    const float* c = S[mf][2 * kch + half];
                    float x0 = c[0] * b0s, x1 = c[1] * b0s;
                    float x2 = c[2] * b1s, x3 = c[3] * b1s;
                    __nv_bfloat162 t0 = __floats2bfloat162_rn(x0, x1);
                    __nv_bfloat162 t1 = __floats2bfloat162_rn(x2, x3);
                    __nv_bfloat162 u0 = __floats2bfloat162_rn(
                        x0 - __bfloat162float(t0.x), x1 - __bfloat162float(t0.y));
                    __nv_bfloat162 u1 = __floats2bfloat162_rn(
                        x2 - __bfloat162float(t1.x), x3 - __bfloat162float(t1.y));
                    P0[mf][half * 2 + 0] = *(uint32_t*)&t0;
                    P0[mf][half * 2 + 1] = *(uint32_t*)&t1;
                    P1[mf][half * 2 + 0] = *(uint32_t*)&u0;
                    P1[mf][half * 2 + 1] = *(uint32_t*)&u1;
                }
            }
#pragma unroll
            for (int dnp = 0; dnp < 4; ++dnp) {
                uint32_t V0[4], V1[4];
                const uint32_t va = vst
                    + (wn * 64 + kch * 16 + ((lane >> 4) & 1) * 8 + (lane & 7)) * 144
                    + dnp * 32 + ((lane >> 3) & 1) * 16;
                ldsm4t(V0, va);
                ldsm4t(V1, va + ATILE);
                // product-major: same-acc reuse distance 4
#pragma unroll
                for (int mf = 0; mf < 2; ++mf) {      // p0 v0
                    hmma(O[mf][2 * dnp + 0], P0[mf], V0[0], V0[2]);
                    hmma(O[mf][2 * dnp + 1], P0[mf], V0[1], V0[3]);
                }
#pragma unroll
                for (int mf = 0; mf < 2; ++mf) {      // p0 v1
                    hmma(O[mf][2 * dnp + 0], P0[mf], V1[0], V1[2]);
                    hmma(O[mf][2 * dnp + 1], P0[mf], V1[1], V1[3]);
                }
#pragma unroll
                for (int mf = 0; mf < 2; ++mf) {      // p1 v0
                    hmma(O[mf][2 * dnp + 0], P1[mf], V0[0], V0[2]);
                    hmma(O[mf][2 * dnp + 1], P1[mf], V0[1], V0[3]);
                }
            }
        }
        // no end barrier: next iter's barrier A protects V buffer reuse
    }

    // ---- epilogue: reduce across wn, normalize, write 2-limb bf16 ctx ----
    __syncthreads();
    float* osm = (float*)smem;     // [128][64]
    if (wn == 1) {
#pragma unroll
        for (int mf = 0; mf < 2; ++mf)
#pragma unroll
            for (int rh = 0; rh < 2; ++rh) {
                const int row = wm * 32 + mf * 16 + rh * 8 + rloc;
#pragma unroll
                for (int dn = 0; dn < 8; ++dn) {
                    const int col = dn * 8 + (lane & 3) * 2;
                    *(float2*)(osm + row * 64 + col) =
                        make_float2(O[mf][dn][rh * 2 + 0], O[mf][dn][rh * 2 + 1]);
                }
            }
    }
    __syncthreads();
    if (wn == 0) {
#pragma unroll
        for (int mf = 0; mf < 2; ++mf)
#pragma unroll
            for (int rh = 0; rh < 2; ++rh) {
                const int sl  = mf * 2 + rh;
                const int row = wm * 32 + mf * 16 + rh * 8 + rloc;
                const float inv = 1.0f / lst[sl];
                const size_t obase = hb + (size_t)(q0r + row) * HH;
#pragma unroll
                for (int dn = 0; dn < 8; ++dn) {
                    const int col = dn * 8 + (lane & 3) * 2;
                    float2 ov = *(float2*)(osm + row * 64 + col);
                    float x = (O[mf][dn][rh * 2 + 0] + ov.x) * inv;
                    float y = (O[mf][dn][rh * 2 + 1] + ov.y) * inv;
                    __nv_bfloat162 h0 = __floats2bfloat162_rn(x, y);
                    __nv_bfloat162 g0 = __floats2bfloat162_rn(
                        x - __bfloat162float(h0.x), y - __bfloat162float(h0.y));
                    *(uint32_t*)(cx0 + obase + col) = *(uint32_t*)&h0;
                    *(uint32_t*)(cx1 + obase + col) = *(uint32_t*)&g0;
                }
            }
    }
}

// ---------------------------------------------------------------------------
// Launch
// ---------------------------------------------------------------------------
extern "C" void kernel_launch(void* const* d_in, const int* in_sizes, int n_in,
                              void* d_out, int out_size)
{
    const float* hs  = (const float*)d_in[0];
    const float* msk = (const float*)d_in[1];
    const float* q_s = (const float*)d_in[2];
    const float* q_d = (const float*)d_in[3];
    const float* k_s = (const float*)d_in[4];
    const float* k_d = (const float*)d_in[5];
    const float* v_s = (const float*)d_in[6];
    const float* v_d = (const float*)d_in[7];
    const float* o_s = (const float*)d_in[8];
    const float* o_d = (const float*)d_in[9];
    float* out = (float*)d_out;

    void* p;
    cudaGetSymbolAddress(&p, g_hs);  bf16* hsL = (bf16*)p;
    cudaGetSymbolAddress(&p, g_wsp); bf16* wsp = (bf16*)p;
    cudaGetSymbolAddress(&p, g_qkv); bf16* qkv = (bf16*)p;
    cudaGetSymbolAddress(&p, g_cx);  bf16* cxL = (bf16*)p;

    const size_t AE = (size_t)MM * HH;
    const size_t WE = (size_t)HH * HH;
    bf16 *hs0 = hsL, *hs1 = hsL + AE, *hs2 = hsL + 2 * AE;
    bf16 *wq0 = wsp,          *wq1 = wsp + WE,      *wq2 = wsp + 2 * WE;
    bf16 *wk0 = wsp + 3 * WE, *wk1 = wsp + 4 * WE,  *wk2 = wsp + 5 * WE;
    bf16 *wv0 = wsp + 6 * WE, *wv1 = wsp + 7 * WE,  *wv2 = wsp + 8 * WE;
    bf16 *wo0 = wsp + 9 * WE, *wo1 = wsp + 10 * WE, *wo2 = wsp + 11 * WE;
    bf16 *pq0 = qkv,          *pq1 = qkv + AE;
    bf16 *pk0 = qkv + 2 * AE, *pk1 = qkv + 3 * AE;
    bf16 *pv0 = qkv + 4 * AE, *pv1 = qkv + 5 * AE;
    bf16 *cx0 = cxL,          *cx1 = cxL + AE;

    // Splits
    split_hs<<<(int)(AE / 4 / 256), 256>>>((const float4*)hs, hs0, hs1, hs2,
                                           (int)(AE / 4));
    WSplitArgs wa;
    wa.a[0] = (const float4*)q_s; wa.b[0] = (const float4*)q_d;
    wa.l0[0] = wq0; wa.l1[0] = wq1; wa.l2[0] = wq2;
    wa.a[1] = (const float4*)k_s; wa.b[1] = (const float4*)k_d;
    wa.l0[1] = wk0; wa.l1[1] = wk1; wa.l2[1] = wk2;
    wa.a[2] = (const float4*)v_s; wa.b[2] = (const float4*)v_d;
    wa.l0[2] = wv0; wa.l1[2] = wv1; wa.l2[2] = wv2;
    wa.a[3] = (const float4*)o_s; wa.b[3] = (const float4*)o_d;
    wa.l0[3] = wo0; wa.l1[3] = wo1; wa.l2[3] = wo2;
    split_w4<<<dim3((int)(WE / 4 / 256), 4), 256>>>(wa, (int)(WE / 4));

    // GEMMs: K16 4-stage pipeline, 2 CTAs/SM
    const int SMEM3 = 4 * 6 * 4096;   // 98304
    const int SMEM2 = 4 * 4 * 4096;   // 65536
    cudaFuncSetAttribute(mma_gemm<3, true>,  cudaFuncAttributeMaxDynamicSharedMemorySize, SMEM3);
    cudaFuncSetAttribute(mma_gemm<2, true>,  cudaFuncAttributeMaxDynamicSharedMemorySize, SMEM2);
    cudaFuncSetAttribute(mma_gemm<2, false>, cudaFuncAttributeMaxDynamicSharedMemorySize, SMEM2);
    dim3 gg(HH / 128, MM / 128);

    mma_gemm<3, true><<<gg, 256, SMEM3>>>(hs0, hs1, hs2, wq0, wq1, wq2,
                                          nullptr, pq0, pq1);
    mma_gemm<3, true><<<gg, 256, SMEM3>>>(hs0, hs1, hs2, wk0, wk1, wk2,
                                          nullptr, pk0, pk1);
    mma_gemm<2, true><<<gg, 256, SMEM2>>>(hs0, hs1, nullptr, wv0, wv1, nullptr,
                                          nullptr, pv0, pv1);

    // Attention: 256 threads, 8 warps
    const int attn_smem = 4 * KSTAGE + 2 * ATILE + 2048;   // 186368
    cudaFuncSetAttribute(attn_mma, cudaFuncAttributeMaxDynamicSharedMemorySize,
                         attn_smem);
    dim3 agrid(SS / 128, NHH, BB);
    attn_mma<<<agrid, 256, attn_smem>>>(pq0, pq1, pk0, pk1, pv0, pv1, msk,
                                        cx0, cx1);

    // O projection
    mma_gemm<2, false><<<gg, 256, SMEM2>>>(cx0, cx1, nullptr, wo0, wo1, nullptr,
                                           out, nullptr, nullptr);
}

// round 14
// speedup vs baseline: 1.1165x; 1.1165x over previous
#include <cuda_runtime.h>
#include <cuda_bf16.h>
#include <math.h>
#include <stdint.h>

// Problem constants
#define BB   2
#define SS   2048
#define HH   1024
#define NHH  16
#define HDD  64
#define MM   (BB * SS)          // 4096 rows

typedef __nv_bfloat16 bf16;

// ---------------------------------------------------------------------------
// Scratch (device globals: allocation-free contract)
// ---------------------------------------------------------------------------
__device__ __align__(256) bf16 g_hs[3][MM * HH];
__device__ __align__(256) bf16 g_wsp[12][HH * HH];
__device__ __align__(256) bf16 g_qkv[6][MM * HH];   // q0,q1,k0,k1,v0,v1
__device__ __align__(256) bf16 g_cx[2][MM * HH];    // ctx limbs

// ---------------------------------------------------------------------------
// Limb splits
// ---------------------------------------------------------------------------
__device__ __forceinline__ void split3_body(
    float4 a, bf16* L0, bf16* L1, bf16* L2, size_t i)
{
    float v[4] = {a.x, a.y, a.z, a.w};
    __align__(8) bf16 o0[4], o1[4], o2[4];
#pragma unroll
    for (int t = 0; t < 4; ++t) {
        float x = v[t];
        bf16 c0 = __float2bfloat16(x);
        float r = x - __bfloat162float(c0);
        bf16 c1 = __float2bfloat16(r);
        r -= __bfloat162float(c1);
        bf16 c2 = __float2bfloat16(r);
        o0[t] = c0; o1[t] = c1; o2[t] = c2;
    }
    *(uint2*)(L0 + 4 * i) = *(uint2*)o0;
    *(uint2*)(L1 + 4 * i) = *(uint2*)o1;
    *(uint2*)(L2 + 4 * i) = *(uint2*)o2;
}

__global__ void __launch_bounds__(256) split_hs(
    const float4* __restrict__ A,
    bf16* __restrict__ L0, bf16* __restrict__ L1, bf16* __restrict__ L2, int n4)
{
    int i = blockIdx.x * 256 + threadIdx.x;
    if (i >= n4) return;
    split3_body(A[i], L0, L1, L2, (size_t)i);
}

struct WSplitArgs {
    const float4* a[4];
    const float4* b[4];
    bf16 *l0[4], *l1[4], *l2[4];
};

__global__ void __launch_bounds__(256) split_w4(WSplitArgs args, int n4)
{
    const int t = blockIdx.y;
    int i = blockIdx.x * 256 + threadIdx.x;
    if (i >= n4) return;
    float4 a = args.a[t][i];
    float4 b = args.b[t][i];
    a.x += b.x; a.y += b.y; a.z += b.z; a.w += b.w;
    split3_body(a, args.l0[t], args.l1[t], args.l2[t], (size_t)i);
}

// ---------------------------------------------------------------------------
// mma.sync helpers
// ---------------------------------------------------------------------------
__device__ __forceinline__ void ldsm4(uint32_t* r, uint32_t addr) {
    asm volatile("ldmatrix.sync.aligned.m8n8.x4.shared.b16 {%0,%1,%2,%3}, [%4];"
                 : "=r"(r[0]), "=r"(r[1]), "=r"(r[2]), "=r"(r[3]) : "r"(addr));
}
__device__ __forceinline__ void ldsm4t(uint32_t* r, uint32_t addr) {
    asm volatile("ldmatrix.sync.aligned.m8n8.x4.trans.shared.b16 {%0,%1,%2,%3}, [%4];"
                 : "=r"(r[0]), "=r"(r[1]), "=r"(r[2]), "=r"(r[3]) : "r"(addr));
}
__device__ __forceinline__ void hmma(float* c, const uint32_t* a,
                                     uint32_t b0, uint32_t b1) {
    asm volatile(
        "mma.sync.aligned.m16n8k16.row.col.f32.bf16.bf16.f32 "
        "{%0,%1,%2,%3}, {%4,%5,%6,%7}, {%8,%9}, {%0,%1,%2,%3};"
        : "+f"(c[0]), "+f"(c[1]), "+f"(c[2]), "+f"(c[3])
        : "r"(a[0]), "r"(a[1]), "r"(a[2]), "r"(a[3]), "r"(b0), "r"(b1));
}

// ---------------------------------------------------------------------------
// HMMA multi-limb GEMM (R11 config — measured best: 131us, tensor 64.4%).
// 2 CTAs/SM. Swizzled smem: tile = 128 rows x 64B, phys chunk = ch^((r>>1)&3).
// 2-stage K32 pipeline, one barrier per stage. 8 warps (2x4), warp 64x32.
// ---------------------------------------------------------------------------
template <int NL, bool LIMB>
__global__ void __launch_bounds__(256, 2) mma_gemm(
    const bf16* __restrict__ a0, const bf16* __restrict__ a1,
    const bf16* __restrict__ a2,
    const bf16* __restrict__ b0, const bf16* __restrict__ b1,
    const bf16* __restrict__ b2,
    float* __restrict__ C, bf16* __restrict__ L0, bf16* __restrict__ L1)
{
    constexpr int NT     = 2 * NL;
    constexpr int TILEB  = 128 * 64;      // 8192
    constexpr int STAGEB = NT * TILEB;

    extern __shared__ __align__(128) char smem[];
    const uint32_t sb = (uint32_t)__cvta_generic_to_shared(smem);

    const int tid  = threadIdx.x;
    const int lane = tid & 31;
    const int wid  = tid >> 5;
    const int wm   = wid >> 2;
    const int wn   = wid & 3;
    const int m0   = blockIdx.y * 128;
    const int n0   = blockIdx.x * 128;

    const bf16* srcs[NT];
    srcs[0] = a0 + (size_t)m0 * 1024;
    srcs[1] = a1 + (size_t)m0 * 1024;
    if constexpr (NL == 3) {
        srcs[2] = a2 + (size_t)m0 * 1024;
        srcs[3] = b0 + (size_t)n0 * 1024;
        srcs[4] = b1 + (size_t)n0 * 1024;
        srcs[5] = b2 + (size_t)n0 * 1024;
    } else {
        srcs[2] = b0 + (size_t)n0 * 1024;
        srcs[3] = b1 + (size_t)n0 * 1024;
    }

    auto load_stage = [&](int s) {
        const int k0 = s * 32;
        const uint32_t dstb = sb + (s & 1) * STAGEB;
#pragma unroll
        for (int i = 0; i < NT * 2; ++i) {
            const int idx = tid + 256 * i;
            const int t   = idx >> 9;              // 512 chunks per tile
            const int c   = idx & 511;
            const int row = c >> 2;
            const int ch  = c & 3;
            const uint32_t phys = (uint32_t)(row * 64 + ((ch ^ ((row >> 1) & 3)) << 4));
            uint32_t dst = dstb + t * TILEB + phys;
            const void* src = srcs[t] + (size_t)row * 1024 + k0 + ch * 8;
            asm volatile("cp.async.cg.shared.global [%0], [%1], 16;"
                         :: "r"(dst), "l"(src) : "memory");
        }
        asm volatile("cp.async.commit_group;" ::: "memory");
    };

    float acc[4][4][4];
#pragma unroll
    for (int mf = 0; mf < 4; ++mf)
#pragma unroll
        for (int nf = 0; nf < 4; ++nf)
#pragma unroll
            for (int r = 0; r < 4; ++r) acc[mf][nf][r] = 0.0f;

    load_stage(0);

    for (int s = 0; s < 32; ++s) {
        asm volatile("cp.async.wait_group 0;" ::: "memory");
        __syncthreads();
        if (s + 1 < 32) load_stage(s + 1);

        const uint32_t st = sb + (s & 1) * STAGEB;
#pragma unroll
        for (int kh = 0; kh < 2; ++kh) {
            uint32_t Af[NL][4][4];
            uint32_t Bf[NL][2][4];
#pragma unroll
            for (int l = 0; l < NL; ++l) {
#pragma unroll
                for (int mf = 0; mf < 4; ++mf) {
                    const int r  = wm * 64 + mf * 16 + (lane & 15);
                    const int ch = kh * 2 + ((lane >> 4) & 1);
                    ldsm4(Af[l][mf], st + l * TILEB
                          + r * 64 + ((ch ^ ((r >> 1) & 3)) << 4));
                }
#pragma unroll
                for (int pr = 0; pr < 2; ++pr) {
                    const int r  = wn * 32 + pr * 16 + ((lane >> 4) & 1) * 8 + (lane & 7);
                    const int ch = kh * 2 + ((lane >> 3) & 1);
                    ldsm4(Bf[l][pr], st + (NL + l) * TILEB
                          + r * 64 + ((ch ^ ((r >> 1) & 3)) << 4));
                }
            }
#pragma unroll
            for (int i = 0; i < NL; ++i)
#pragma unroll
                for (int j = 0; j < NL; ++j) {
                    if (i + j >= NL) continue;
#pragma unroll
                    for (int mf = 0; mf < 4; ++mf)
#pragma unroll
                        for (int pr = 0; pr < 2; ++pr) {
                            hmma(acc[mf][pr * 2 + 0], Af[i][mf], Bf[j][pr][0], Bf[j][pr][1]);
                            hmma(acc[mf][pr * 2 + 1], Af[i][mf], Bf[j][pr][2], Bf[j][pr][3]);
                        }
                }
        }
    }

    const int mrow = m0 + wm * 64 + (lane >> 2);
    const int ncol = n0 + wn * 32 + (lane & 3) * 2;
#pragma unroll
    for (int mf = 0; mf < 4; ++mf)
#pragma unroll
        for (int nf = 0; nf < 4; ++nf) {
            const size_t r0 = (size_t)(mrow + mf * 16) * 1024 + ncol + nf * 8;
            const size_t r1 = r0 + 8 * 1024;
            if constexpr (LIMB) {
                float v0 = acc[mf][nf][0], v1 = acc[mf][nf][1];
                float v2 = acc[mf][nf][2], v3 = acc[mf][nf][3];
                __nv_bfloat162 h0 = __floats2bfloat162_rn(v0, v1);
                __nv_bfloat162 g0 = __floats2bfloat162_rn(
                    v0 - __bfloat162float(h0.x), v1 - __bfloat162float(h0.y));
                __nv_bfloat162 h1 = __floats2bfloat162_rn(v2, v3);
                __nv_bfloat162 g1 = __floats2bfloat162_rn(
                    v2 - __bfloat162float(h1.x), v3 - __bfloat162float(h1.y));
                *(uint32_t*)(L0 + r0) = *(uint32_t*)&h0;
                *(uint32_t*)(L1 + r0) = *(uint32_t*)&g0;
                *(uint32_t*)(L0 + r1) = *(uint32_t*)&h1;
                *(uint32_t*)(L1 + r1) = *(uint32_t*)&g1;
            } else {
                *(float2*)(C + r0) = make_float2(acc[mf][nf][0], acc[mf][nf][1]);
                *(float2*)(C + r1) = make_float2(acc[mf][nf][2], acc[mf][nf][3]);
            }
        }
}

// ---------------------------------------------------------------------------
// HMMA flash attention (256-thread / 8-warp — measured best):
// wm=wid>>1 (32 q-rows), wn=wid&1 (64 k-cols). Split K/V prefetch,
// single-pass softmax merge, 2 barriers per iteration. 144B-padded rows.
// Product-major HMMA ordering (same-acc distance 4).
// ---------------------------------------------------------------------------
#define ATILE  18432          // 128 rows * 144B
#define KSTAGE (2 * ATILE)    // 2 limbs

__global__ void __launch_bounds__(256, 1) attn_mma(
    const bf16* __restrict__ q0l, const bf16* __restrict__ q1l,
    const bf16* __restrict__ k0l, const bf16* __restrict__ k1l,
    const bf16* __restrict__ v0l, const bf16* __restrict__ v1l,
    const float* __restrict__ mask,
    bf16* __restrict__ cx0, bf16* __restrict__ cx1)
{
    extern __shared__ __align__(128) char smem[];
    const uint32_t sb = (uint32_t)__cvta_generic_to_shared(smem);
    const uint32_t kK   = sb;                        // K: 2 stages x 2 limbs
    const uint32_t kV   = sb + 2 * KSTAGE;           // V: 2 stages x 2 limbs
    const uint32_t qbse = sb + 4 * KSTAGE;           // Q: 2 limbs
    float* red = (float*)(smem + 4 * KSTAGE + 2 * ATILE);  // [2][128][2] (m,l)

    const int tid  = threadIdx.x;
    const int lane = tid & 31;
    const int wid  = tid >> 5;
    const int wm   = wid >> 1;
    const int wn   = wid & 1;
    const int qt = blockIdx.x, h = blockIdx.y, b = blockIdx.z;
    const int q0r = qt * 128;

    const size_t hb = (size_t)b * SS * HH + (size_t)h * HDD;
    const bf16* qsrc[2] = {q0l + hb + (size_t)q0r * HH, q1l + hb + (size_t)q0r * HH};
    const bf16* ksrc[2] = {k0l + hb, k1l + hb};
    const bf16* vsrc[2] = {v0l + hb, v1l + hb};
    const float* maskb = mask + (size_t)b * SS * SS;

    auto load_k = [&](int s) {
        const int k00 = s * 128;
        const uint32_t dstb = kK + (s & 1) * KSTAGE;
#pragma unroll
        for (int i = 0; i < 8; ++i) {
            const int idx = tid + 256 * i;
            const int limb = idx >> 10;
            const int rem  = idx & 1023;
            const int r = rem >> 3, c = rem & 7;
            uint32_t dst = dstb + limb * ATILE + r * 144 + c * 16;
            const void* src = ksrc[limb] + (size_t)(k00 + r) * HH + c * 8;
            asm volatile("cp.async.cg.shared.global [%0], [%1], 16;"
                         :: "r"(dst), "l"(src) : "memory");
        }
    };
    auto load_v = [&](int s) {
        const int k00 = s * 128;
        const uint32_t dstb = kV + (s & 1) * KSTAGE;
#pragma unroll
        for (int i = 0; i < 8; ++i) {
            const int idx = tid + 256 * i;
            const int limb = idx >> 10;
            const int rem  = idx & 1023;
            const int r = rem >> 3, c = rem & 7;
            uint32_t dst = dstb + limb * ATILE + r * 144 + c * 16;
            const void* src = vsrc[limb] + (size_t)(k00 + r) * HH + c * 8;
            asm volatile("cp.async.cg.shared.global [%0], [%1], 16;"
                         :: "r"(dst), "l"(src) : "memory");
        }
    };

    // Prologue: G0 = {Q, K0, V0}; G1 = {K1}
#pragma unroll
    for (int i = 0; i < 8; ++i) {
        const int idx = tid + 256 * i;
        const int limb = idx >> 10;
        const int rem  = idx & 1023;
        const int r = rem >> 3, c = rem & 7;
        uint32_t dst = qbse + limb * ATILE + r * 144 + c * 16;
        const void* src = qsrc[limb] + (size_t)r * HH + c * 8;
        asm volatile("cp.async.cg.shared.global [%0], [%1], 16;"
                     :: "r"(dst), "l"(src) : "memory");
    }
    load_k(0);
    load_v(0);
    asm volatile("cp.async.commit_group;" ::: "memory");
    load_k(1);
    asm volatile("cp.async.commit_group;" ::: "memory");

    float O[2][8][4];
#pragma unroll
    for (int mf = 0; mf < 2; ++mf)
#pragma unroll
        for (int dn = 0; dn < 8; ++dn)
#pragma unroll
            for (int r = 0; r < 4; ++r) O[mf][dn][r] = 0.0f;
    float mst[4] = {-INFINITY, -INFINITY, -INFINITY, -INFINITY};
    float lst[4] = {0.0f, 0.0f, 0.0f, 0.0f};

    const int rloc = (lane >> 2);
    const float scale = 0.125f;

    for (int s = 0; s < 16; ++s) {
        if (s < 15) asm volatile("cp.async.wait_group 1;" ::: "memory");
        else        asm volatile("cp.async.wait_group 0;" ::: "memory");
        __syncthreads();                              // barrier A

        if (s + 1 < 16) {
            load_v(s + 1);
            asm volatile("cp.async.commit_group;" ::: "memory");
        }

        const uint32_t kst = kK + (s & 1) * KSTAGE;
        const uint32_t vst = kV + (s & 1) * KSTAGE;

        // ---- QK^T ----
        float S[2][8][4];
#pragma unroll
        for (int mf = 0; mf < 2; ++mf)
#pragma unroll
            for (int nf = 0; nf < 8; ++nf)
#pragma unroll
                for (int r = 0; r < 4; ++r) S[mf][nf][r] = 0.0f;

#pragma unroll
        for (int ch = 0; ch < 4; ++ch) {
            uint32_t A[2][2][4];
#pragma unroll
            for (int l = 0; l < 2; ++l)
#pragma unroll
                for (int mf = 0; mf < 2; ++mf)
                    ldsm4(A[l][mf], qbse + l * ATILE
                          + (wm * 32 + mf * 16 + (lane & 15)) * 144
                          + ch * 32 + ((lane >> 4) & 1) * 16);
#pragma unroll
            for (int bp = 0; bp < 4; ++bp) {
                uint32_t B0[4], B1[4];
                const uint32_t ba = kst
                    + (wn * 64 + bp * 16 + ((lane >> 4) & 1) * 8 + (lane & 7)) * 144
                    + ((lane >> 3) & 1) * 16 + ch * 32;
                ldsm4(B0, ba);
                ldsm4(B1, ba + ATILE);
                // product-major: same-acc reuse distance 4
#pragma unroll
                for (int mf = 0; mf < 2; ++mf) {      // q0k0
                    hmma(S[mf][2 * bp + 0], A[0][mf], B0[0], B0[1]);
                    hmma(S[mf][2 * bp + 1], A[0][mf], B0[2], B0[3]);
                }
#pragma unroll
                for (int mf = 0; mf < 2; ++mf) {      // q0k1
                    hmma(S[mf][2 * bp + 0], A[0][mf], B1[0], B1[1]);
                    hmma(S[mf][2 * bp + 1], A[0][mf], B1[2], B1[3]);
                }
#pragma unroll
                for (int mf = 0; mf < 2; ++mf) {      // q1k0
                    hmma(S[mf][2 * bp + 0], A[1][mf], B0[0], B0[1]);
                    hmma(S[mf][2 * bp + 1], A[1][mf], B0[2], B0[3]);
                }
            }
        }

        // ---- scale + mask + local max ----
        float mloc[4] = {-INFINITY, -INFINITY, -INFINITY, -INFINITY};
#pragma unroll
        for (int mf = 0; mf < 2; ++mf)
#pragma unroll
            for (int rh = 0; rh < 2; ++rh) {
                const int row = q0r + wm * 32 + mf * 16 + rh * 8 + rloc;
                const float* mrp = maskb + (size_t)row * SS + s * 128 + wn * 64
                                   + (lane & 3) * 2;
                const int sl = mf * 2 + rh;
#pragma unroll
                for (int nf = 0; nf < 8; ++nf) {
                    float2 mv = *(const float2*)(mrp + nf * 8);
                    float a = fmaf(S[mf][nf][rh * 2 + 0], scale, mv.x);
                    float c = fmaf(S[mf][nf][rh * 2 + 1], scale, mv.y);
                    S[mf][nf][rh * 2 + 0] = a;
                    S[mf][nf][rh * 2 + 1] = c;
                    mloc[sl] = fmaxf(mloc[sl], fmaxf(a, c));
                }
            }
#pragma unroll
        for (int off = 1; off < 4; off <<= 1)
#pragma unroll
            for (int sl = 0; sl < 4; ++sl)
                mloc[sl] = fmaxf(mloc[sl], __shfl_xor_sync(0xffffffffu, mloc[sl], off));

        // ---- exp with LOCAL max + local sum (pre-barrier) ----
        float lw[4];
#pragma unroll
        for (int mf = 0; mf < 2; ++mf)
#pragma unroll
            for (int rh = 0; rh < 2; ++rh) {
                const int sl = mf * 2 + rh;
                float ls = 0.0f;
#pragma unroll
                for (int nf = 0; nf < 8; ++nf) {
                    float a = __expf(S[mf][nf][rh * 2 + 0] - mloc[sl]);
                    float c = __expf(S[mf][nf][rh * 2 + 1] - mloc[sl]);
                    S[mf][nf][rh * 2 + 0] = a;
                    S[mf][nf][rh * 2 + 1] = c;
                    ls += a + c;
                }
                lw[sl] = ls;
            }
#pragma unroll
        for (int off = 1; off < 4; off <<= 1)
#pragma unroll
            for (int sl = 0; sl < 4; ++sl)
                lw[sl] += __shfl_xor_sync(0xffffffffu, lw[sl], off);

        if ((lane & 3) == 0) {
#pragma unroll
            for (int mf = 0; mf < 2; ++mf)
#pragma unroll
                for (int rh = 0; rh < 2; ++rh) {
                    const int rr = wm * 32 + mf * 16 + rh * 8 + rloc;
                    red[wn * 256 + rr * 2 + 0] = mloc[mf * 2 + rh];
                    red[wn * 256 + rr * 2 + 1] = lw[mf * 2 + rh];
                }
        }
        __syncthreads();                              // barrier B

        if (s + 2 < 16) {
            load_k(s + 2);
            asm volatile("cp.async.commit_group;" ::: "memory");
        }

        // ---- cross-half merge ----
        float alpha[4], beta[4];
#pragma unroll
        for (int mf = 0; mf < 2; ++mf)
#pragma unroll
            for (int rh = 0; rh < 2; ++rh) {
                const int sl = mf * 2 + rh;
                const int rr = wm * 32 + mf * 16 + rh * 8 + rloc;
                const float mp = red[(wn ^ 1) * 256 + rr * 2 + 0];
                const float lp = red[(wn ^ 1) * 256 + rr * 2 + 1];
                const float mnew = fmaxf(mst[sl], fmaxf(mloc[sl], mp));
                alpha[sl] = __expf(mst[sl] - mnew);
                beta[sl]  = __expf(mloc[sl] - mnew);
                lst[sl] = lst[sl] * alpha[sl] + lw[sl] * beta[sl]
                          + lp * __expf(mp - mnew);
                mst[sl] = mnew;
            }
#pragma unroll
        for (int mf = 0; mf < 2; ++mf)
#pragma unroll
            for (int dn = 0; dn < 8; ++dn) {
                O[mf][dn][0] *= alpha[mf * 2 + 0];
                O[mf][dn][1] *= alpha[mf * 2 + 0];
                O[mf][dn][2] *= alpha[mf * 2 + 1];
                O[mf][dn][3] *= alpha[mf * 2 + 1];
            }

        // ---- PV (P scaled by beta during frag build) ----
#pragma unroll
        for (int kch = 0; kch < 4; ++kch) {
            uint32_t P0[2][4], P1[2][4];
#pragma unroll
            for (int mf = 0; mf < 2; ++mf) {
                const float b0s = beta[mf * 2 + 0];
                const float b1s = beta[mf * 2 + 1];
#pragma unroll
                for (int half = 0; half < 2; ++half) {
                    const float* c = S[mf][2 * kch + half];
                    float x0 = c[0] * b0s, x1 = c[1] * b0s;
                    float x2 = c[2] * b1s, x3 = c[3] * b1s;
                    __nv_bfloat162 t0 = __floats2bfloat162_rn(x0, x1);
                    __nv_bfloat162 t1 = __floats2bfloat162_rn(x2, x3);
                    __nv_bfloat162 u0 = __floats2bfloat162_rn(
                        x0 - __bfloat162float(t0.x), x1 - __bfloat162float(t0.y));
                    __nv_bfloat162 u1 = __floats2bfloat162_rn(
                        x2 - __bfloat162float(t1.x), x3 - __bfloat162float(t1.y));
                    P0[mf][half * 2 + 0] = *(uint32_t*)&t0;
                    P0[mf][half * 2 + 1] = *(uint32_t*)&t1;
                    P1[mf][half * 2 + 0] = *(uint32_t*)&u0;
                    P1[mf][half * 2 + 1] = *(uint32_t*)&u1;
                }
            }
#pragma unroll
            for (int dnp = 0; dnp < 4; ++dnp) {
                uint32_t V0[4], V1[4];
                const uint32_t va = vst
                    + (wn * 64 + kch * 16 + ((lane >> 4) & 1) * 8 + (lane & 7)) * 144
                    + dnp * 32 + ((lane >> 3) & 1) * 16;
                ldsm4t(V0, va);
                ldsm4t(V1, va + ATILE);
                // product-major: same-acc reuse distance 4
#pragma unroll
                for (int mf = 0; mf < 2; ++mf) {      // p0 v0
                    hmma(O[mf][2 * dnp + 0], P0[mf], V0[0], V0[2]);
                    hmma(O[mf][2 * dnp + 1], P0[mf], V0[1], V0[3]);
                }
#pragma unroll
                for (int mf = 0; mf < 2; ++mf) {      // p0 v1
                    hmma(O[mf][2 * dnp + 0], P0[mf], V1[0], V1[2]);
                    hmma(O[mf][2 * dnp + 1], P0[mf], V1[1], V1[3]);
                }
#pragma unroll
                for (int mf = 0; mf < 2; ++mf) {      // p1 v0
                    hmma(O[mf][2 * dnp + 0], P1[mf], V0[0], V0[2]);
                    hmma(O[mf][2 * dnp + 1], P1[mf], V0[1], V0[3]);
                }
            }
        }
        // no end barrier: next iter's barrier A protects V buffer reuse
    }

    // ---- epilogue: reduce across wn, normalize, write 2-limb bf16 ctx ----
    __syncthreads();
    float* osm = (float*)smem;     // [128][64]
    if (wn == 1) {
#pragma unroll
        for (int mf = 0; mf < 2; ++mf)
#pragma unroll
            for (int rh = 0; rh < 2; ++rh) {
                const int row = wm * 32 + mf * 16 + rh * 8 + rloc;
#pragma unroll
                for (int dn = 0; dn < 8; ++dn) {
                    const int col = dn * 8 + (lane & 3) * 2;
                    *(float2*)(osm + row * 64 + col) =
                        make_float2(O[mf][dn][rh * 2 + 0], O[mf][dn][rh * 2 + 1]);
                }
            }
    }
    __syncthreads();
    if (wn == 0) {
#pragma unroll
        for (int mf = 0; mf < 2; ++mf)
#pragma unroll
            for (int rh = 0; rh < 2; ++rh) {
                const int sl  = mf * 2 + rh;
                const int row = wm * 32 + mf * 16 + rh * 8 + rloc;
                const float inv = 1.0f / lst[sl];
                const size_t obase = hb + (size_t)(q0r + row) * HH;
#pragma unroll
                for (int dn = 0; dn < 8; ++dn) {
                    const int col = dn * 8 + (lane & 3) * 2;
                    float2 ov = *(float2*)(osm + row * 64 + col);
                    float x = (O[mf][dn][rh * 2 + 0] + ov.x) * inv;
                    float y = (O[mf][dn][rh * 2 + 1] + ov.y) * inv;
                    __nv_bfloat162 h0 = __floats2bfloat162_rn(x, y);
                    __nv_bfloat162 g0 = __floats2bfloat162_rn(
                        x - __bfloat162float(h0.x), y - __bfloat162float(h0.y));
                    *(uint32_t*)(cx0 + obase + col) = *(uint32_t*)&h0;
                    *(uint32_t*)(cx1 + obase + col) = *(uint32_t*)&g0;
                }
            }
    }
}

// ---------------------------------------------------------------------------
// Launch
// ---------------------------------------------------------------------------
extern "C" void kernel_launch(void* const* d_in, const int* in_sizes, int n_in,
                              void* d_out, int out_size)
{
    const float* hs  = (const float*)d_in[0];
    const float* msk = (const float*)d_in[1];
    const float* q_s = (const float*)d_in[2];
    const float* q_d = (const float*)d_in[3];
    const float* k_s = (const float*)d_in[4];
    const float* k_d = (const float*)d_in[5];
    const float* v_s = (const float*)d_in[6];
    const float* v_d = (const float*)d_in[7];
    const float* o_s = (const float*)d_in[8];
    const float* o_d = (const float*)d_in[9];
    float* out = (float*)d_out;

    void* p;
    cudaGetSymbolAddress(&p, g_hs);  bf16* hsL = (bf16*)p;
    cudaGetSymbolAddress(&p, g_wsp); bf16* wsp = (bf16*)p;
    cudaGetSymbolAddress(&p, g_qkv); bf16* qkv = (bf16*)p;
    cudaGetSymbolAddress(&p, g_cx);  bf16* cxL = (bf16*)p;

    const size_t AE = (size_t)MM * HH;
    const size_t WE = (size_t)HH * HH;
    bf16 *hs0 = hsL, *hs1 = hsL + AE, *hs2 = hsL + 2 * AE;
    bf16 *wq0 = wsp,          *wq1 = wsp + WE,      *wq2 = wsp + 2 * WE;
    bf16 *wk0 = wsp + 3 * WE, *wk1 = wsp + 4 * WE,  *wk2 = wsp + 5 * WE;
    bf16 *wv0 = wsp + 6 * WE, *wv1 = wsp + 7 * WE,  *wv2 = wsp + 8 * WE;
    bf16 *wo0 = wsp + 9 * WE, *wo1 = wsp + 10 * WE, *wo2 = wsp + 11 * WE;
    bf16 *pq0 = qkv,          *pq1 = qkv + AE;
    bf16 *pk0 = qkv + 2 * AE, *pk1 = qkv + 3 * AE;
    bf16 *pv0 = qkv + 4 * AE, *pv1 = qkv + 5 * AE;
    bf16 *cx0 = cxL,          *cx1 = cxL + AE;

    // Splits
    split_hs<<<(int)(AE / 4 / 256), 256>>>((const float4*)hs, hs0, hs1, hs2,
                                           (int)(AE / 4));
    WSplitArgs wa;
    wa.a[0] = (const float4*)q_s; wa.b[0] = (const float4*)q_d;
    wa.l0[0] = wq0; wa.l1[0] = wq1; wa.l2[0] = wq2;
    wa.a[1] = (const float4*)k_s; wa.b[1] = (const float4*)k_d;
    wa.l0[1] = wk0; wa.l1[1] = wk1; wa.l2[1] = wk2;
    wa.a[2] = (const float4*)v_s; wa.b[2] = (const float4*)v_d;
    wa.l0[2] = wv0; wa.l1[2] = wv1; wa.l2[2] = wv2;
    wa.a[3] = (const float4*)o_s; wa.b[3] = (const float4*)o_d;
    wa.l0[3] = wo0; wa.l1[3] = wo1; wa.l2[3] = wo2;
    split_w4<<<dim3((int)(WE / 4 / 256), 4), 256>>>(wa, (int)(WE / 4));

    // GEMMs: K32 2-stage swizzled, 2 CTAs/SM (R11 config)
    const int SMEM3 = 2 * 6 * 8192;   // 98304
    const int SMEM2 = 2 * 4 * 8192;   // 65536
    cudaFuncSetAttribute(mma_gemm<3, true>,  cudaFuncAttributeMaxDynamicSharedMemorySize, SMEM3);
    cudaFuncSetAttribute(mma_gemm<2, true>,  cudaFuncAttributeMaxDynamicSharedMemorySize, SMEM2);
    cudaFuncSetAttribute(mma_gemm<2, false>, cudaFuncAttributeMaxDynamicSharedMemorySize, SMEM2);
    dim3 gg(HH / 128, MM / 128);

    mma_gemm<3, true><<<gg, 256, SMEM3>>>(hs0, hs1, hs2, wq0, wq1, wq2,
                                          nullptr, pq0, pq1);
    mma_gemm<3, true><<<gg, 256, SMEM3>>>(hs0, hs1, hs2, wk0, wk1, wk2,
                                          nullptr, pk0, pk1);
    mma_gemm<2, true><<<gg, 256, SMEM2>>>(hs0, hs1, nullptr, wv0, wv1, nullptr,
                                          nullptr, pv0, pv1);

    // Attention: 256 threads, 8 warps
    const int attn_smem = 4 * KSTAGE + 2 * ATILE + 2048;   // 186368
    cudaFuncSetAttribute(attn_mma, cudaFuncAttributeMaxDynamicSharedMemorySize,
                         attn_smem);
    dim3 agrid(SS / 128, NHH, BB);
    attn_mma<<<agrid, 256, attn_smem>>>(pq0, pq1, pk0, pk1, pv0, pv1, msk,
                                        cx0, cx1);

    // O projection
    mma_gemm<2, false><<<gg, 256, SMEM2>>>(cx0, cx1, nullptr, wo0, wo1, nullptr,
                                           out, nullptr, nullptr);
}

// round 15
// speedup vs baseline: 1.2728x; 1.1400x over previous
#include <cuda_runtime.h>
#include <cuda_fp16.h>
#include <math.h>
#include <stdint.h>

// Problem constants
#define BB   2
#define SS   2048
#define HH   1024
#define NHH  16
#define HDD  64
#define MM   (BB * SS)          // 4096 rows

// ---------------------------------------------------------------------------
// Scratch (device globals: allocation-free contract)
// ---------------------------------------------------------------------------
__device__ __align__(256) __half g_hs[2][MM * HH];     // hs limbs
__device__ __align__(256) __half g_wsp[8][HH * HH];    // q(0,1) k(2,3) v(4,5) o(6,7)
__device__ __align__(256) __half g_qkv[6][MM * HH];    // q0,q1,k0,k1,v0,v1
__device__ __align__(256) __half g_cx[2][MM * HH];     // ctx limbs

// ---------------------------------------------------------------------------
// Limb splits (fp16 2-limb, exact residual chain)
// ---------------------------------------------------------------------------
__device__ __forceinline__ void split2_body(
    float4 a, __half* L0, __half* L1, size_t i)
{
    float v[4] = {a.x, a.y, a.z, a.w};
    __align__(8) __half o0[4], o1[4];
#pragma unroll
    for (int t = 0; t < 4; ++t) {
        float x = v[t];
        __half c0 = __float2half_rn(x);
        float r = x - __half2float(c0);
        o0[t] = c0;
        o1[t] = __float2half_rn(r);
    }
    *(uint2*)(L0 + 4 * i) = *(uint2*)o0;
    *(uint2*)(L1 + 4 * i) = *(uint2*)o1;
}

__global__ void __launch_bounds__(256) split_hs(
    const float4* __restrict__ A,
    __half* __restrict__ L0, __half* __restrict__ L1, int n4)
{
    int i = blockIdx.x * 256 + threadIdx.x;
    if (i >= n4) return;
    split2_body(A[i], L0, L1, (size_t)i);
}

struct WSplitArgs {
    const float4* a[4];
    const float4* b[4];
    __half *l0[4], *l1[4];
};

__global__ void __launch_bounds__(256) split_w4(WSplitArgs args, int n4)
{
    const int t = blockIdx.y;
    int i = blockIdx.x * 256 + threadIdx.x;
    if (i >= n4) return;
    float4 a = args.a[t][i];
    float4 b = args.b[t][i];
    a.x += b.x; a.y += b.y; a.z += b.z; a.w += b.w;
    split2_body(a, args.l0[t], args.l1[t], (size_t)i);
}

// ---------------------------------------------------------------------------
// mma.sync helpers (fp16)
// ---------------------------------------------------------------------------
__device__ __forceinline__ void ldsm4(uint32_t* r, uint32_t addr) {
    asm volatile("ldmatrix.sync.aligned.m8n8.x4.shared.b16 {%0,%1,%2,%3}, [%4];"
                 : "=r"(r[0]), "=r"(r[1]), "=r"(r[2]), "=r"(r[3]) : "r"(addr));
}
__device__ __forceinline__ void ldsm4t(uint32_t* r, uint32_t addr) {
    asm volatile("ldmatrix.sync.aligned.m8n8.x4.trans.shared.b16 {%0,%1,%2,%3}, [%4];"
                 : "=r"(r[0]), "=r"(r[1]), "=r"(r[2]), "=r"(r[3]) : "r"(addr));
}
__device__ __forceinline__ void hmma(float* c, const uint32_t* a,
                                     uint32_t b0, uint32_t b1) {
    asm volatile(
        "mma.sync.aligned.m16n8k16.row.col.f32.f16.f16.f32 "
        "{%0,%1,%2,%3}, {%4,%5,%6,%7}, {%8,%9}, {%0,%1,%2,%3};"
        : "+f"(c[0]), "+f"(c[1]), "+f"(c[2]), "+f"(c[3])
        : "r"(a[0]), "r"(a[1]), "r"(a[2]), "r"(a[3]), "r"(b0), "r"(b1));
}

// ---------------------------------------------------------------------------
// HMMA 2-limb fp16 GEMM (R11/R14 proven config, NL=2 only).
// 2 CTAs/SM. Swizzled smem: tile = 128 rows x 64B, phys chunk = ch^((r>>1)&3).
// 2-stage K32 pipeline, one barrier per stage. 8 warps (2x4), warp 64x32.
// 3 limb products: a0b0 + a0b1 + a1b0 (a1b1 ~2^-22 omitted).
// ---------------------------------------------------------------------------
template <bool LIMB>
__global__ void __launch_bounds__(256, 2) mma_gemm(
    const __half* __restrict__ a0, const __half* __restrict__ a1,
    const __half* __restrict__ b0, const __half* __restrict__ b1,
    float* __restrict__ C, __half* __restrict__ L0, __half* __restrict__ L1)
{
    constexpr int NT     = 4;
    constexpr int TILEB  = 128 * 64;      // 8192
    constexpr int STAGEB = NT * TILEB;

    extern __shared__ __align__(128) char smem[];
    const uint32_t sb = (uint32_t)__cvta_generic_to_shared(smem);

    const int tid  = threadIdx.x;
    const int lane = tid & 31;
    const int wid  = tid >> 5;
    const int wm   = wid >> 2;
    const int wn   = wid & 3;
    const int m0   = blockIdx.y * 128;
    const int n0   = blockIdx.x * 128;

    const __half* srcs[NT];
    srcs[0] = a0 + (size_t)m0 * 1024;
    srcs[1] = a1 + (size_t)m0 * 1024;
    srcs[2] = b0 + (size_t)n0 * 1024;
    srcs[3] = b1 + (size_t)n0 * 1024;

    auto load_stage = [&](int s) {
        const int k0 = s * 32;
        const uint32_t dstb = sb + (s & 1) * STAGEB;
#pragma unroll
        for (int i = 0; i < NT * 2; ++i) {
            const int idx = tid + 256 * i;
            const int t   = idx >> 9;              // 512 chunks per tile
            const int c   = idx & 511;
            const int row = c >> 2;
            const int ch  = c & 3;
            const uint32_t phys = (uint32_t)(row * 64 + ((ch ^ ((row >> 1) & 3)) << 4));
            uint32_t dst = dstb + t * TILEB + phys;
            const void* src = srcs[t] + (size_t)row * 1024 + k0 + ch * 8;
            asm volatile("cp.async.cg.shared.global [%0], [%1], 16;"
                         :: "r"(dst), "l"(src) : "memory");
        }
        asm volatile("cp.async.commit_group;" ::: "memory");
    };

    float acc[4][4][4];
#pragma unroll
    for (int mf = 0; mf < 4; ++mf)
#pragma unroll
        for (int nf = 0; nf < 4; ++nf)
#pragma unroll
            for (int r = 0; r < 4; ++r) acc[mf][nf][r] = 0.0f;

    load_stage(0);

    for (int s = 0; s < 32; ++s) {
        asm volatile("cp.async.wait_group 0;" ::: "memory");
        __syncthreads();
        if (s + 1 < 32) load_stage(s + 1);

        const uint32_t st = sb + (s & 1) * STAGEB;
#pragma unroll
        for (int kh = 0; kh < 2; ++kh) {
            uint32_t Af[2][4][4];
            uint32_t Bf[2][2][4];
#pragma unroll
            for (int l = 0; l < 2; ++l) {
#pragma unroll
                for (int mf = 0; mf < 4; ++mf) {
                    const int r  = wm * 64 + mf * 16 + (lane & 15);
                    const int ch = kh * 2 + ((lane >> 4) & 1);
                    ldsm4(Af[l][mf], st + l * TILEB
                          + r * 64 + ((ch ^ ((r >> 1) & 3)) << 4));
                }
#pragma unroll
                for (int pr = 0; pr < 2; ++pr) {
                    const int r  = wn * 32 + pr * 16 + ((lane >> 4) & 1) * 8 + (lane & 7);
                    const int ch = kh * 2 + ((lane >> 3) & 1);
                    ldsm4(Bf[l][pr], st + (2 + l) * TILEB
                          + r * 64 + ((ch ^ ((r >> 1) & 3)) << 4));
                }
            }
            // products: (0,0), (0,1), (1,0)
#pragma unroll
            for (int i = 0; i < 2; ++i)
#pragma unroll
                for (int j = 0; j < 2; ++j) {
                    if (i + j >= 2) continue;
#pragma unroll
                    for (int mf = 0; mf < 4; ++mf)
#pragma unroll
                        for (int pr = 0; pr < 2; ++pr) {
                            hmma(acc[mf][pr * 2 + 0], Af[i][mf], Bf[j][pr][0], Bf[j][pr][1]);
                            hmma(acc[mf][pr * 2 + 1], Af[i][mf], Bf[j][pr][2], Bf[j][pr][3]);
                        }
                }
        }
    }

    const int mrow = m0 + wm * 64 + (lane >> 2);
    const int ncol = n0 + wn * 32 + (lane & 3) * 2;
#pragma unroll
    for (int mf = 0; mf < 4; ++mf)
#pragma unroll
        for (int nf = 0; nf < 4; ++nf) {
            const size_t r0 = (size_t)(mrow + mf * 16) * 1024 + ncol + nf * 8;
            const size_t r1 = r0 + 8 * 1024;
            if constexpr (LIMB) {
                float v0 = acc[mf][nf][0], v1 = acc[mf][nf][1];
                float v2 = acc[mf][nf][2], v3 = acc[mf][nf][3];
                __half2 h0 = __floats2half2_rn(v0, v1);
                __half2 g0 = __floats2half2_rn(
                    v0 - __half2float(h0.x), v1 - __half2float(h0.y));
                __half2 h1 = __floats2half2_rn(v2, v3);
                __half2 g1 = __floats2half2_rn(
                    v2 - __half2float(h1.x), v3 - __half2float(h1.y));
                *(uint32_t*)(L0 + r0) = *(uint32_t*)&h0;
                *(uint32_t*)(L1 + r0) = *(uint32_t*)&g0;
                *(uint32_t*)(L0 + r1) = *(uint32_t*)&h1;
                *(uint32_t*)(L1 + r1) = *(uint32_t*)&g1;
            } else {
                *(float2*)(C + r0) = make_float2(acc[mf][nf][0], acc[mf][nf][1]);
                *(float2*)(C + r1) = make_float2(acc[mf][nf][2], acc[mf][nf][3]);
            }
        }
}

// ---------------------------------------------------------------------------
// HMMA flash attention (256-thread / 8-warp proven config, fp16 limbs):
// wm=wid>>1 (32 q-rows), wn=wid&1 (64 k-cols). Split K/V prefetch,
// single-pass softmax merge, 2 barriers per iteration. 144B-padded rows.
// Product-major HMMA ordering (same-acc distance 4).
// ---------------------------------------------------------------------------
#define ATILE  18432          // 128 rows * 144B
#define KSTAGE (2 * ATILE)    // 2 limbs

__global__ void __launch_bounds__(256, 1) attn_mma(
    const __half* __restrict__ q0l, const __half* __restrict__ q1l,
    const __half* __restrict__ k0l, const __half* __restrict__ k1l,
    const __half* __restrict__ v0l, const __half* __restrict__ v1l,
    const float* __restrict__ mask,
    __half* __restrict__ cx0, __half* __restrict__ cx1)
{
    extern __shared__ __align__(128) char smem[];
    const uint32_t sb = (uint32_t)__cvta_generic_to_shared(smem);
    const uint32_t kK   = sb;                        // K: 2 stages x 2 limbs
    const uint32_t kV   = sb + 2 * KSTAGE;           // V: 2 stages x 2 limbs
    const uint32_t qbse = sb + 4 * KSTAGE;           // Q: 2 limbs
    float* red = (float*)(smem + 4 * KSTAGE + 2 * ATILE);  // [2][128][2] (m,l)

    const int tid  = threadIdx.x;
    const int lane = tid & 31;
    const int wid  = tid >> 5;
    const int wm   = wid >> 1;
    const int wn   = wid & 1;
    const int qt = blockIdx.x, h = blockIdx.y, b = blockIdx.z;
    const int q0r = qt * 128;

    const size_t hb = (size_t)b * SS * HH + (size_t)h * HDD;
    const __half* qsrc[2] = {q0l + hb + (size_t)q0r * HH, q1l + hb + (size_t)q0r * HH};
    const __half* ksrc[2] = {k0l + hb, k1l + hb};
    const __half* vsrc[2] = {v0l + hb, v1l + hb};
    const float* maskb = mask + (size_t)b * SS * SS;

    auto load_k = [&](int s) {
        const int k00 = s * 128;
        const uint32_t dstb = kK + (s & 1) * KSTAGE;
#pragma unroll
        for (int i = 0; i < 8; ++i) {
            const int idx = tid + 256 * i;
            const int limb = idx >> 10;
            const int rem  = idx & 1023;
            const int r = rem >> 3, c = rem & 7;
            uint32_t dst = dstb + limb * ATILE + r * 144 + c * 16;
            const void* src = ksrc[limb] + (size_t)(k00 + r) * HH + c * 8;
            asm volatile("cp.async.cg.shared.global [%0], [%1], 16;"
                         :: "r"(dst), "l"(src) : "memory");
        }
    };
    auto load_v = [&](int s) {
        const int k00 = s * 128;
        const uint32_t dstb = kV + (s & 1) * KSTAGE;
#pragma unroll
        for (int i = 0; i < 8; ++i) {
            const int idx = tid + 256 * i;
            const int limb = idx >> 10;
            const int rem  = idx & 1023;
            const int r = rem >> 3, c = rem & 7;
            uint32_t dst = dstb + limb * ATILE + r * 144 + c * 16;
            const void* src = vsrc[limb] + (size_t)(k00 + r) * HH + c * 8;
            asm volatile("cp.async.cg.shared.global [%0], [%1], 16;"
                         :: "r"(dst), "l"(src) : "memory");
        }
    };

    // Prologue: G0 = {Q, K0, V0}; G1 = {K1}
#pragma unroll
    for (int i = 0; i < 8; ++i) {
        const int idx = tid + 256 * i;
        const int limb = idx >> 10;
        const int rem  = idx & 1023;
        const int r = rem >> 3, c = rem & 7;
        uint32_t dst = qbse + limb * ATILE + r * 144 + c * 16;
        const void* src = qsrc[limb] + (size_t)r * HH + c * 8;
        asm volatile("cp.async.cg.shared.global [%0], [%1], 16;"
                     :: "r"(dst), "l"(src) : "memory");
    }
    load_k(0);
    load_v(0);
    asm volatile("cp.async.commit_group;" ::: "memory");
    load_k(1);
    asm volatile("cp.async.commit_group;" ::: "memory");

    float O[2][8][4];
#pragma unroll
    for (int mf = 0; mf < 2; ++mf)
#pragma unroll
        for (int dn = 0; dn < 8; ++dn)
#pragma unroll
            for (int r = 0; r < 4; ++r) O[mf][dn][r] = 0.0f;
    float mst[4] = {-INFINITY, -INFINITY, -INFINITY, -INFINITY};
    float lst[4] = {0.0f, 0.0f, 0.0f, 0.0f};

    const int rloc = (lane >> 2);
    const float scale = 0.125f;

    for (int s = 0; s < 16; ++s) {
        if (s < 15) asm volatile("cp.async.wait_group 1;" ::: "memory");
        else        asm volatile("cp.async.wait_group 0;" ::: "memory");
        __syncthreads();                              // barrier A

        if (s + 1 < 16) {
            load_v(s + 1);
            asm volatile("cp.async.commit_group;" ::: "memory");
        }

        const uint32_t kst = kK + (s & 1) * KSTAGE;
        const uint32_t vst = kV + (s & 1) * KSTAGE;

        // ---- QK^T ----
        float S[2][8][4];
#pragma unroll
        for (int mf = 0; mf < 2; ++mf)
#pragma unroll
            for (int nf = 0; nf < 8; ++nf)
#pragma unroll
                for (int r = 0; r < 4; ++r) S[mf][nf][r] = 0.0f;

#pragma unroll
        for (int ch = 0; ch < 4; ++ch) {
            uint32_t A[2][2][4];
#pragma unroll
            for (int l = 0; l < 2; ++l)
#pragma unroll
                for (int mf = 0; mf < 2; ++mf)
                    ldsm4(A[l][mf], qbse + l * ATILE
                          + (wm * 32 + mf * 16 + (lane & 15)) * 144
                          + ch * 32 + ((lane >> 4) & 1) * 16);
#pragma unroll
            for (int bp = 0; bp < 4; ++bp) {
                uint32_t B0[4], B1[4];
                const uint32_t ba = kst
                    + (wn * 64 + bp * 16 + ((lane >> 4) & 1) * 8 + (lane & 7)) * 144
                    + ((lane >> 3) & 1) * 16 + ch * 32;
                ldsm4(B0, ba);
                ldsm4(B1, ba + ATILE);
                // product-major: same-acc reuse distance 4
#pragma unroll
                for (int mf = 0; mf < 2; ++mf) {      // q0k0
                    hmma(S[mf][2 * bp + 0], A[0][mf], B0[0], B0[1]);
                    hmma(S[mf][2 * bp + 1], A[0][mf], B0[2], B0[3]);
                }
#pragma unroll
                for (int mf = 0; mf < 2; ++mf) {      // q0k1
                    hmma(S[mf][2 * bp + 0], A[0][mf], B1[0], B1[1]);
                    hmma(S[mf][2 * bp + 1], A[0][mf], B1[2], B1[3]);
                }
#pragma unroll
                for (int mf = 0; mf < 2; ++mf) {      // q1k0
                    hmma(S[mf][2 * bp + 0], A[1][mf], B0[0], B0[1]);
                    hmma(S[mf][2 * bp + 1], A[1][mf], B0[2], B0[3]);
                }
            }
        }

        // ---- scale + mask + local max ----
        float mloc[4] = {-INFINITY, -INFINITY, -INFINITY, -INFINITY};
#pragma unroll
        for (int mf = 0; mf < 2; ++mf)
#pragma unroll
            for (int rh = 0; rh < 2; ++rh) {
                const int row = q0r + wm * 32 + mf * 16 + rh * 8 + rloc;
                const float* mrp = maskb + (size_t)row * SS + s * 128 + wn * 64
                                   + (lane & 3) * 2;
                const int sl = mf * 2 + rh;
#pragma unroll
                for (int nf = 0; nf < 8; ++nf) {
                    float2 mv = *(const float2*)(mrp + nf * 8);
                    float a = fmaf(S[mf][nf][rh * 2 + 0], scale, mv.x);
                    float c = fmaf(S[mf][nf][rh * 2 + 1], scale, mv.y);
                    S[mf][nf][rh * 2 + 0] = a;
                    S[mf][nf][rh * 2 + 1] = c;
                    mloc[sl] = fmaxf(mloc[sl], fmaxf(a, c));
                }
            }
#pragma unroll
        for (int off = 1; off < 4; off <<= 1)
#pragma unroll
            for (int sl = 0; sl < 4; ++sl)
                mloc[sl] = fmaxf(mloc[sl], __shfl_xor_sync(0xffffffffu, mloc[sl], off));

        // ---- exp with LOCAL max + local sum (pre-barrier) ----
        float lw[4];
#pragma unroll
        for (int mf = 0; mf < 2; ++mf)
#pragma unroll
            for (int rh = 0; rh < 2; ++rh) {
                const int sl = mf * 2 + rh;
                float ls = 0.0f;
#pragma unroll
                for (int nf = 0; nf < 8; ++nf) {
                    float a = __expf(S[mf][nf][rh * 2 + 0] - mloc[sl]);
                    float c = __expf(S[mf][nf][rh * 2 + 1] - mloc[sl]);
                    S[mf][nf][rh * 2 + 0] = a;
                    S[mf][nf][rh * 2 + 1] = c;
                    ls += a + c;
                }
                lw[sl] = ls;
            }
#pragma unroll
        for (int off = 1; off < 4; off <<= 1)
#pragma unroll
            for (int sl = 0; sl < 4; ++sl)
                lw[sl] += __shfl_xor_sync(0xffffffffu, lw[sl], off);

        if ((lane & 3) == 0) {
#pragma unroll
            for (int mf = 0; mf < 2; ++mf)
#pragma unroll
                for (int rh = 0; rh < 2; ++rh) {
                    const int rr = wm * 32 + mf * 16 + rh * 8 + rloc;
                    red[wn * 256 + rr * 2 + 0] = mloc[mf * 2 + rh];
                    red[wn * 256 + rr * 2 + 1] = lw[mf * 2 + rh];
                }
        }
        __syncthreads();                              // barrier B

        if (s + 2 < 16) {
            load_k(s + 2);
            asm volatile("cp.async.commit_group;" ::: "memory");
        }

        // ---- cross-half merge ----
        float alpha[4], beta[4];
#pragma unroll
        for (int mf = 0; mf < 2; ++mf)
#pragma unroll
            for (int rh = 0; rh < 2; ++rh) {
                const int sl = mf * 2 + rh;
                const int rr = wm * 32 + mf * 16 + rh * 8 + rloc;
                const float mp = red[(wn ^ 1) * 256 + rr * 2 + 0];
                const float lp = red[(wn ^ 1) * 256 + rr * 2 + 1];
                const float mnew = fmaxf(mst[sl], fmaxf(mloc[sl], mp));
                alpha[sl] = __expf(mst[sl] - mnew);
                beta[sl]  = __expf(mloc[sl] - mnew);
                lst[sl] = lst[sl] * alpha[sl] + lw[sl] * beta[sl]
                          + lp * __expf(mp - mnew);
                mst[sl] = mnew;
            }
#pragma unroll
        for (int mf = 0; mf < 2; ++mf)
#pragma unroll
            for (int dn = 0; dn < 8; ++dn) {
                O[mf][dn][0] *= alpha[mf * 2 + 0];
                O[mf][dn][1] *= alpha[mf * 2 + 0];
                O[mf][dn][2] *= alpha[mf * 2 + 1];
                O[mf][dn][3] *= alpha[mf * 2 + 1];
            }

        // ---- PV (P scaled by beta during frag build) ----
#pragma unroll
        for (int kch = 0; kch < 4; ++kch) {
            uint32_t P0[2][4], P1[2][4];
#pragma unroll
            for (int mf = 0; mf < 2; ++mf) {
                const float b0s = beta[mf * 2 + 0];
                const float b1s = beta[mf * 2 + 1];
#pragma unroll
                for (int half = 0; half < 2; ++half) {
                    const float* c = S[mf][2 * kch + half];
                    float x0 = c[0] * b0s, x1 = c[1] * b0s;
                    float x2 = c[2] * b1s, x3 = c[3] * b1s;
                    __half2 t0 = __floats2half2_rn(x0, x1);
                    __half2 t1 = __floats2half2_rn(x2, x3);
                    __half2 u0 = __floats2half2_rn(
                        x0 - __half2float(t0.x), x1 - __half2float(t0.y));
                    __half2 u1 = __floats2half2_rn(
                        x2 - __half2float(t1.x), x3 - __half2float(t1.y));
                    P0[mf][half * 2 + 0] = *(uint32_t*)&t0;
                    P0[mf][half * 2 + 1] = *(uint32_t*)&t1;
                    P1[mf][half * 2 + 0] = *(uint32_t*)&u0;
                    P1[mf][half * 2 + 1] = *(uint32_t*)&u1;
                }
            }
#pragma unroll
            for (int dnp = 0; dnp < 4; ++dnp) {
                uint32_t V0[4], V1[4];
                const uint32_t va = vst
                    + (wn * 64 + kch * 16 + ((lane >> 4) & 1) * 8 + (lane & 7)) * 144
                    + dnp * 32 + ((lane >> 3) & 1) * 16;
                ldsm4t(V0, va);
                ldsm4t(V1, va + ATILE);
                // product-major: same-acc reuse distance 4
#pragma unroll
                for (int mf = 0; mf < 2; ++mf) {      // p0 v0
                    hmma(O[mf][2 * dnp + 0], P0[mf], V0[0], V0[2]);
                    hmma(O[mf][2 * dnp + 1], P0[mf], V0[1], V0[3]);
                }
#pragma unroll
                for (int mf = 0; mf < 2; ++mf) {      // p0 v1
                    hmma(O[mf][2 * dnp + 0], P0[mf], V1[0], V1[2]);
                    hmma(O[mf][2 * dnp + 1], P0[mf], V1[1], V1[3]);
                }
#pragma unroll
                for (int mf = 0; mf < 2; ++mf) {      // p1 v0
                    hmma(O[mf][2 * dnp + 0], P1[mf], V0[0], V0[2]);
                    hmma(O[mf][2 * dnp + 1], P1[mf], V0[1], V0[3]);
                }
            }
        }
        // no end barrier: next iter's barrier A protects V buffer reuse
    }

    // ---- epilogue: reduce across wn, normalize, write 2-limb fp16 ctx ----
    __syncthreads();
    float* osm = (float*)smem;     // [128][64]
    if (wn == 1) {
#pragma unroll
        for (int mf = 0; mf < 2; ++mf)
#pragma unroll
            for (int rh = 0; rh < 2; ++rh) {
                const int row = wm * 32 + mf * 16 + rh * 8 + rloc;
#pragma unroll
                for (int dn = 0; dn < 8; ++dn) {
                    const int col = dn * 8 + (lane & 3) * 2;
                    *(float2*)(osm + row * 64 + col) =
                        make_float2(O[mf][dn][rh * 2 + 0], O[mf][dn][rh * 2 + 1]);
                }
            }
    }
    __syncthreads();
    if (wn == 0) {
#pragma unroll
        for (int mf = 0; mf < 2; ++mf)
#pragma unroll
            for (int rh = 0; rh < 2; ++rh) {
                const int sl  = mf * 2 + rh;
                const int row = wm * 32 + mf * 16 + rh * 8 + rloc;
                const float inv = 1.0f / lst[sl];
                const size_t obase = hb + (size_t)(q0r + row) * HH;
#pragma unroll
                for (int dn = 0; dn < 8; ++dn) {
                    const int col = dn * 8 + (lane & 3) * 2;
                    float2 ov = *(float2*)(osm + row * 64 + col);
                    float x = (O[mf][dn][rh * 2 + 0] + ov.x) * inv;
                    float y = (O[mf][dn][rh * 2 + 1] + ov.y) * inv;
                    __half2 h0 = __floats2half2_rn(x, y);
                    __half2 g0 = __floats2half2_rn(
                        x - __half2float(h0.x), y - __half2float(h0.y));
                    *(uint32_t*)(cx0 + obase + col) = *(uint32_t*)&h0;
                    *(uint32_t*)(cx1 + obase + col) = *(uint32_t*)&g0;
                }
            }
    }
}

// ---------------------------------------------------------------------------
// Launch
// ---------------------------------------------------------------------------
extern "C" void kernel_launch(void* const* d_in, const int* in_sizes, int n_in,
                              void* d_out, int out_size)
{
    const float* hs  = (const float*)d_in[0];
    const float* msk = (const float*)d_in[1];
    const float* q_s = (const float*)d_in[2];
    const float* q_d = (const float*)d_in[3];
    const float* k_s = (const float*)d_in[4];
    const float* k_d = (const float*)d_in[5];
    const float* v_s = (const float*)d_in[6];
    const float* v_d = (const float*)d_in[7];
    const float* o_s = (const float*)d_in[8];
    const float* o_d = (const float*)d_in[9];
    float* out = (float*)d_out;

    void* p;
    cudaGetSymbolAddress(&p, g_hs);  __half* hsL = (__half*)p;
    cudaGetSymbolAddress(&p, g_wsp); __half* wsp = (__half*)p;
    cudaGetSymbolAddress(&p, g_qkv); __half* qkv = (__half*)p;
    cudaGetSymbolAddress(&p, g_cx);  __half* cxL = (__half*)p;

    const size_t AE = (size_t)MM * HH;
    const size_t WE = (size_t)HH * HH;
    __half *hs0 = hsL, *hs1 = hsL + AE;
    __half *wq0 = wsp,          *wq1 = wsp + WE;
    __half *wk0 = wsp + 2 * WE, *wk1 = wsp + 3 * WE;
    __half *wv0 = wsp + 4 * WE, *wv1 = wsp + 5 * WE;
    __half *wo0 = wsp + 6 * WE, *wo1 = wsp + 7 * WE;
    __half *pq0 = qkv,          *pq1 = qkv + AE;
    __half *pk0 = qkv + 2 * AE, *pk1 = qkv + 3 * AE;
    __half *pv0 = qkv + 4 * AE, *pv1 = qkv + 5 * AE;
    __half *cx0 = cxL,          *cx1 = cxL + AE;

    // Splits (fp16 2-limb)
    split_hs<<<(int)(AE / 4 / 256), 256>>>((const float4*)hs, hs0, hs1,
                                           (int)(AE / 4));
    WSplitArgs wa;
    wa.a[0] = (const float4*)q_s; wa.b[0] = (const float4*)q_d;
    wa.l0[0] = wq0; wa.l1[0] = wq1;
    wa.a[1] = (const float4*)k_s; wa.b[1] = (const float4*)k_d;
    wa.l0[1] = wk0; wa.l1[1] = wk1;
    wa.a[2] = (const float4*)v_s; wa.b[2] = (const float4*)v_d;
    wa.l0[2] = wv0; wa.l1[2] = wv1;
    wa.a[3] = (const float4*)o_s; wa.b[3] = (const float4*)o_d;
    wa.l0[3] = wo0; wa.l1[3] = wo1;
    split_w4<<<dim3((int)(WE / 4 / 256), 4), 256>>>(wa, (int)(WE / 4));

    // GEMMs: fp16 NL=2, K32 2-stage swizzled, 2 CTAs/SM
    const int SMEM2 = 2 * 4 * 8192;   // 65536
    cudaFuncSetAttribute(mma_gemm<true>,  cudaFuncAttributeMaxDynamicSharedMemorySize, SMEM2);
    cudaFuncSetAttribute(mma_gemm<false>, cudaFuncAttributeMaxDynamicSharedMemorySize, SMEM2);
    dim3 gg(HH / 128, MM / 128);

    mma_gemm<true><<<gg, 256, SMEM2>>>(hs0, hs1, wq0, wq1, nullptr, pq0, pq1);
    mma_gemm<true><<<gg, 256, SMEM2>>>(hs0, hs1, wk0, wk1, nullptr, pk0, pk1);
    mma_gemm<true><<<gg, 256, SMEM2>>>(hs0, hs1, wv0, wv1, nullptr, pv0, pv1);

    // Attention: 256 threads, 8 warps
    const int attn_smem = 4 * KSTAGE + 2 * ATILE + 2048;   // 186368
    cudaFuncSetAttribute(attn_mma, cudaFuncAttributeMaxDynamicSharedMemorySize,
                         attn_smem);
    dim3 agrid(SS / 128, NHH, BB);
    attn_mma<<<agrid, 256, attn_smem>>>(pq0, pq1, pk0, pk1, pv0, pv1, msk,
                                        cx0, cx1);

    // O projection
    mma_gemm<false><<<gg, 256, SMEM2>>>(cx0, cx1, wo0, wo1, out, nullptr, nullptr);
}